// round 1
// baseline (speedup 1.0000x reference)
#include <cuda_runtime.h>

#define BB 32
#define CC 512
#define HC 128
#define HW 4096
#define EPS_BN 0.001f

// scratch (no allocations allowed in kernel_launch)
__device__ float g_s[BB * CC];      // pooled means [B, C]
__device__ float g_es[BB * CC];     // e * scale2   [B, C]
__device__ float g_shift[CC];       // shift2       [C]

// ---------------------------------------------------------------------------
// Kernel 1: per-plane mean. One block per (b,c) plane of 4096 floats.
// ---------------------------------------------------------------------------
__global__ void __launch_bounds__(256) se_reduce(const float* __restrict__ x) {
    const int plane = blockIdx.x;  // 0 .. B*C-1
    const float4* xp = reinterpret_cast<const float4*>(x + (size_t)plane * HW);

    float sum = 0.f;
#pragma unroll
    for (int i = 0; i < HW / 4 / 256; i++) {
        float4 v = xp[i * 256 + threadIdx.x];
        sum += (v.x + v.y) + (v.z + v.w);
    }

    // warp reduce
#pragma unroll
    for (int o = 16; o > 0; o >>= 1)
        sum += __shfl_down_sync(0xffffffffu, sum, o);

    __shared__ float red[8];
    if ((threadIdx.x & 31) == 0) red[threadIdx.x >> 5] = sum;
    __syncthreads();
    if (threadIdx.x < 32) {
        float s = (threadIdx.x < 8) ? red[threadIdx.x] : 0.f;
#pragma unroll
        for (int o = 4; o > 0; o >>= 1)
            s += __shfl_down_sync(0xffffffffu, s, o);
        if (threadIdx.x == 0) g_s[plane] = s * (1.0f / HW);
    }
}

// ---------------------------------------------------------------------------
// Kernel 2: excitation MLP. One block per batch row (32 blocks x 128 thr).
//   h = relu(BN1(s @ w1^T)) ; e = h @ w2^T ; es = e*scale2 ; shift = shift2
// ---------------------------------------------------------------------------
__global__ void __launch_bounds__(128) se_excite(
    const float* __restrict__ w1, const float* __restrict__ g1,
    const float* __restrict__ b1, const float* __restrict__ m1,
    const float* __restrict__ v1, const float* __restrict__ w2,
    const float* __restrict__ g2, const float* __restrict__ b2,
    const float* __restrict__ m2, const float* __restrict__ v2) {
    __shared__ float s_s[CC];
    __shared__ float s_h[HC];

    const int b = blockIdx.x;
    for (int i = threadIdx.x; i < CC; i += 128) s_s[i] = g_s[b * CC + i];
    __syncthreads();

    // h[j] for j = threadIdx.x (exactly 128 hidden units)
    {
        const int j = threadIdx.x;
        const float* wr = w1 + j * CC;
        float acc = 0.f;
#pragma unroll 8
        for (int k = 0; k < CC; k++) acc = fmaf(s_s[k], wr[k], acc);
        float hv = (acc - m1[j]) * (g1[j] * rsqrtf(v1[j] + EPS_BN)) + b1[j];
        s_h[j] = fmaxf(hv, 0.f);
    }
    __syncthreads();

    // e[c], folded with BN2 scale
    for (int c = threadIdx.x; c < CC; c += 128) {
        const float* wr = w2 + c * HC;
        float acc = 0.f;
#pragma unroll 8
        for (int k = 0; k < HC; k++) acc = fmaf(s_h[k], wr[k], acc);
        const float sc2 = g2[c] * rsqrtf(v2[c] + EPS_BN);
        g_es[b * CC + c] = acc * sc2;
        if (b == 0) g_shift[c] = fmaf(-m2[c], sc2, b2[c]);
    }
}

// ---------------------------------------------------------------------------
// Kernel 3: y = x * es[b,c] + shift[c]. 4 blocks per plane (block-uniform b,c).
// ---------------------------------------------------------------------------
__global__ void __launch_bounds__(256) se_scale(const float* __restrict__ x,
                                                float* __restrict__ y) {
    const int plane = blockIdx.x >> 2;            // (b*C + c)
    const int part  = blockIdx.x & 3;             // quarter of the plane
    const float es    = g_es[plane];
    const float shift = g_shift[plane & (CC - 1)];

    const size_t base = (size_t)plane * (HW / 4) + (size_t)part * 256;
    const float4* xp = reinterpret_cast<const float4*>(x) + base;
    float4*       yp = reinterpret_cast<float4*>(y) + base;

    float4 v = xp[threadIdx.x];
    float4 o;
    o.x = fmaf(v.x, es, shift);
    o.y = fmaf(v.y, es, shift);
    o.z = fmaf(v.z, es, shift);
    o.w = fmaf(v.w, es, shift);
    yp[threadIdx.x] = o;
}

// ---------------------------------------------------------------------------
extern "C" void kernel_launch(void* const* d_in, const int* in_sizes, int n_in,
                              void* d_out, int out_size) {
    const float* x  = (const float*)d_in[0];
    const float* w1 = (const float*)d_in[1];
    const float* g1 = (const float*)d_in[2];
    const float* b1 = (const float*)d_in[3];
    const float* m1 = (const float*)d_in[4];
    const float* v1 = (const float*)d_in[5];
    const float* w2 = (const float*)d_in[6];
    const float* g2 = (const float*)d_in[7];
    const float* b2 = (const float*)d_in[8];
    const float* m2 = (const float*)d_in[9];
    const float* v2 = (const float*)d_in[10];
    float* y = (float*)d_out;

    se_reduce<<<BB * CC, 256>>>(x);
    se_excite<<<BB, 128>>>(w1, g1, b1, m1, v1, w2, g2, b2, m2, v2);
    se_scale<<<BB * CC * 4, 256>>>(x, y);
}

// round 2
// speedup vs baseline: 1.0346x; 1.0346x over previous
#include <cuda_runtime.h>

#define BB 32
#define CC 512
#define HC 128
#define HW 4096
#define EPS_BN 0.001f

// scratch (no allocations allowed in kernel_launch)
__device__ float g_s[BB * CC];      // pooled means [B, C]
__device__ float g_es[BB * CC];     // e * scale2   [B, C]
__device__ float g_shift[CC];       // shift2       [C]

// ---------------------------------------------------------------------------
// Kernel 1: per-plane mean. One block per (b,c) plane of 4096 floats.
// ---------------------------------------------------------------------------
__global__ void __launch_bounds__(256) se_reduce(const float* __restrict__ x) {
    const int plane = blockIdx.x;  // 0 .. B*C-1
    const float4* xp = reinterpret_cast<const float4*>(x + (size_t)plane * HW);

    float sum = 0.f;
#pragma unroll
    for (int i = 0; i < HW / 4 / 256; i++) {
        float4 v = xp[i * 256 + threadIdx.x];
        sum += (v.x + v.y) + (v.z + v.w);
    }

    // warp reduce
#pragma unroll
    for (int o = 16; o > 0; o >>= 1)
        sum += __shfl_down_sync(0xffffffffu, sum, o);

    __shared__ float red[8];
    if ((threadIdx.x & 31) == 0) red[threadIdx.x >> 5] = sum;
    __syncthreads();
    if (threadIdx.x < 32) {
        float s = (threadIdx.x < 8) ? red[threadIdx.x] : 0.f;
#pragma unroll
        for (int o = 4; o > 0; o >>= 1)
            s += __shfl_down_sync(0xffffffffu, s, o);
        if (threadIdx.x == 0) g_s[plane] = s * (1.0f / HW);
    }
}

// ---------------------------------------------------------------------------
// Kernel 2: excitation MLP. One block per batch row (32 blocks x 128 thr).
// ---------------------------------------------------------------------------
__global__ void __launch_bounds__(128) se_excite(
    const float* __restrict__ w1, const float* __restrict__ g1,
    const float* __restrict__ b1, const float* __restrict__ m1,
    const float* __restrict__ v1, const float* __restrict__ w2,
    const float* __restrict__ g2, const float* __restrict__ b2,
    const float* __restrict__ m2, const float* __restrict__ v2) {
    __shared__ float s_s[CC];
    __shared__ float s_h[HC];

    const int b = blockIdx.x;
    for (int i = threadIdx.x; i < CC; i += 128) s_s[i] = g_s[b * CC + i];
    __syncthreads();

    {
        const int j = threadIdx.x;
        const float* wr = w1 + j * CC;
        float acc = 0.f;
#pragma unroll 8
        for (int k = 0; k < CC; k++) acc = fmaf(s_s[k], wr[k], acc);
        float hv = (acc - m1[j]) * (g1[j] * rsqrtf(v1[j] + EPS_BN)) + b1[j];
        s_h[j] = fmaxf(hv, 0.f);
    }
    __syncthreads();

    for (int c = threadIdx.x; c < CC; c += 128) {
        const float* wr = w2 + c * HC;
        float acc = 0.f;
#pragma unroll 8
        for (int k = 0; k < HC; k++) acc = fmaf(s_h[k], wr[k], acc);
        const float sc2 = g2[c] * rsqrtf(v2[c] + EPS_BN);
        g_es[b * CC + c] = acc * sc2;
        if (b == 0) g_shift[c] = fmaf(-m2[c], sc2, b2[c]);
    }
}

// ---------------------------------------------------------------------------
// Kernel 3: y = x * es[b,c] + shift[c].
// One block per plane; 256 threads x 4 independent float4 each (MLP=4),
// streaming loads/stores to keep dead traffic out of L2 retention.
// ---------------------------------------------------------------------------
__global__ void __launch_bounds__(256) se_scale(const float* __restrict__ x,
                                                float* __restrict__ y) {
    const int plane = blockIdx.x;                 // (b*C + c)
    const float es    = g_es[plane];
    const float shift = g_shift[plane & (CC - 1)];

    const size_t base = (size_t)plane * (HW / 4);
    const float4* xp = reinterpret_cast<const float4*>(x) + base + threadIdx.x;
    float4*       yp = reinterpret_cast<float4*>(y) + base + threadIdx.x;

    // 4 fully independent load/store pairs (front-batched loads)
    float4 v0 = __ldcs(xp + 0 * 256);
    float4 v1 = __ldcs(xp + 1 * 256);
    float4 v2 = __ldcs(xp + 2 * 256);
    float4 v3 = __ldcs(xp + 3 * 256);

    float4 o0, o1, o2, o3;
    o0.x = fmaf(v0.x, es, shift); o0.y = fmaf(v0.y, es, shift);
    o0.z = fmaf(v0.z, es, shift); o0.w = fmaf(v0.w, es, shift);
    o1.x = fmaf(v1.x, es, shift); o1.y = fmaf(v1.y, es, shift);
    o1.z = fmaf(v1.z, es, shift); o1.w = fmaf(v1.w, es, shift);
    o2.x = fmaf(v2.x, es, shift); o2.y = fmaf(v2.y, es, shift);
    o2.z = fmaf(v2.z, es, shift); o2.w = fmaf(v2.w, es, shift);
    o3.x = fmaf(v3.x, es, shift); o3.y = fmaf(v3.y, es, shift);
    o3.z = fmaf(v3.z, es, shift); o3.w = fmaf(v3.w, es, shift);

    __stcs(yp + 0 * 256, o0);
    __stcs(yp + 1 * 256, o1);
    __stcs(yp + 2 * 256, o2);
    __stcs(yp + 3 * 256, o3);
}

// ---------------------------------------------------------------------------
extern "C" void kernel_launch(void* const* d_in, const int* in_sizes, int n_in,
                              void* d_out, int out_size) {
    const float* x  = (const float*)d_in[0];
    const float* w1 = (const float*)d_in[1];
    const float* g1 = (const float*)d_in[2];
    const float* b1 = (const float*)d_in[3];
    const float* m1 = (const float*)d_in[4];
    const float* v1 = (const float*)d_in[5];
    const float* w2 = (const float*)d_in[6];
    const float* g2 = (const float*)d_in[7];
    const float* b2 = (const float*)d_in[8];
    const float* m2 = (const float*)d_in[9];
    const float* v2 = (const float*)d_in[10];
    float* y = (float*)d_out;

    se_reduce<<<BB * CC, 256>>>(x);
    se_excite<<<BB, 128>>>(w1, g1, b1, m1, v1, w2, g2, b2, m2, v2);
    se_scale<<<BB * CC, 256>>>(x, y);
}